// round 1
// baseline (speedup 1.0000x reference)
#include <cuda_runtime.h>
#include <cstdint>
#include <cmath>

#define Bsz 32
#define Tlen 128
#define Dd 192
#define H4d 768
#define Ll 6
#define Vv 32000
#define BT (Bsz*Tlen)            // 4096
#define BTV ((size_t)BT*(size_t)Vv)

// ---------------- scratch (static device globals; no allocation) ----------------
__device__ float g_h[BT*Dd];       // layer activations [B,T,D]
__device__ float g_gx[BT*H4d];     // input-projection pre-gates [B,T,4D]

// ---------------- f32x2 helpers ----------------
__device__ __forceinline__ unsigned long long pack2(float lo, float hi){
    unsigned long long d;
    asm("mov.b64 %0, {%1, %2};" : "=l"(d)
        : "r"(__float_as_uint(lo)), "r"(__float_as_uint(hi)));
    return d;
}
__device__ __forceinline__ float2 unpack2(unsigned long long v){
    unsigned int lo, hi;
    asm("mov.b64 {%0, %1}, %2;" : "=r"(lo), "=r"(hi) : "l"(v));
    return make_float2(__uint_as_float(lo), __uint_as_float(hi));
}
__device__ __forceinline__ void fma2(unsigned long long &d,
                                     unsigned long long a, unsigned long long b){
    asm("fma.rn.f32x2 %0, %1, %2, %3;" : "=l"(d) : "l"(a), "l"(b), "l"(d));
}
__device__ __forceinline__ uint32_t smem_u32(const void* p){
    uint32_t a;
    asm("{ .reg .u64 t; cvta.to.shared.u64 t, %1; cvt.u32.u64 %0, t; }"
        : "=r"(a) : "l"(p));
    return a;
}

// ---------------- embedding ----------------
__global__ void embed_kernel(const int* __restrict__ x,
                             const float* __restrict__ tok,
                             const float* __restrict__ pos){
    int row = blockIdx.x;            // b*T + t
    int t   = row & (Tlen - 1);
    int tid = threadIdx.x;           // 0..191
    int v   = x[row];
    g_h[(size_t)row*Dd + tid] = tok[(size_t)v*Dd + tid] + pos[t*Dd + tid];
}

// ---------------- GEMM: C[M,N] = A[M,192] * Bw[N,192]^T (+ b1[n]+b2[n]) ----------
// 64x64 tile, 256 threads, 4x4 microtile, f32x2 packed accumulators along M.
template<bool BIAS>
__global__ __launch_bounds__(256,1) void gemm_atb(
    const float* __restrict__ A, const float* __restrict__ Bw,
    const float* __restrict__ b1, const float* __restrict__ b2,
    float* __restrict__ C, int N)
{
    __shared__ float As[16][64];
    __shared__ float Bs[16][64];
    const int m0 = blockIdx.y * 64;
    const int n0 = blockIdx.x * 64;
    const int tid = threadIdx.x;
    const int tx = tid & 15;          // n direction
    const int ty = tid >> 4;          // m direction
    const int lrow = tid >> 2;        // 0..63 (tile row for loads)
    const int lc4  = (tid & 3) << 2;  // 0,4,8,12 (k offset for loads)

    const float4* Ald = reinterpret_cast<const float4*>(A + (size_t)(m0 + lrow)*Dd + lc4);
    const float4* Bld = reinterpret_cast<const float4*>(Bw + (size_t)(n0 + lrow)*Dd + lc4);

    unsigned long long acc[2][4];
    #pragma unroll
    for (int i=0;i<2;i++)
        #pragma unroll
        for (int j=0;j<4;j++) acc[i][j] = 0ULL;

    #pragma unroll 1
    for (int k0 = 0; k0 < Dd/16; k0++){
        float4 av = Ald[k0*4];
        float4 bv = Bld[k0*4];
        As[lc4+0][lrow]=av.x; As[lc4+1][lrow]=av.y; As[lc4+2][lrow]=av.z; As[lc4+3][lrow]=av.w;
        Bs[lc4+0][lrow]=bv.x; Bs[lc4+1][lrow]=bv.y; Bs[lc4+2][lrow]=bv.z; Bs[lc4+3][lrow]=bv.w;
        __syncthreads();
        #pragma unroll
        for (int k=0;k<16;k++){
            const unsigned long long* ap =
                reinterpret_cast<const unsigned long long*>(&As[k][ty<<2]);
            unsigned long long a01 = ap[0], a23 = ap[1];
            float4 b4 = *reinterpret_cast<const float4*>(&Bs[k][tx<<2]);
            unsigned long long bd;
            bd = pack2(b4.x, b4.x); fma2(acc[0][0], a01, bd); fma2(acc[1][0], a23, bd);
            bd = pack2(b4.y, b4.y); fma2(acc[0][1], a01, bd); fma2(acc[1][1], a23, bd);
            bd = pack2(b4.z, b4.z); fma2(acc[0][2], a01, bd); fma2(acc[1][2], a23, bd);
            bd = pack2(b4.w, b4.w); fma2(acc[0][3], a01, bd); fma2(acc[1][3], a23, bd);
        }
        __syncthreads();
    }

    float bias[4] = {0.f,0.f,0.f,0.f};
    if (BIAS){
        #pragma unroll
        for (int j=0;j<4;j++){ int n = n0 + (tx<<2) + j; bias[j] = b1[n] + b2[n]; }
    }
    #pragma unroll
    for (int i=0;i<2;i++){
        float2 p0 = unpack2(acc[i][0]);
        float2 p1 = unpack2(acc[i][1]);
        float2 p2 = unpack2(acc[i][2]);
        float2 p3 = unpack2(acc[i][3]);
        float4 lo = make_float4(p0.x+bias[0], p1.x+bias[1], p2.x+bias[2], p3.x+bias[3]);
        float4 hi = make_float4(p0.y+bias[0], p1.y+bias[1], p2.y+bias[2], p3.y+bias[3]);
        size_t base = (size_t)(m0 + (ty<<2) + 2*i)*(size_t)N + n0 + (tx<<2);
        *reinterpret_cast<float4*>(C + base)              = lo;
        *reinterpret_cast<float4*>(C + base + (size_t)N)  = hi;
    }
}

// ---------------- recurrent scan: one cluster (4 CTAs) per batch element --------
// CTA rank r owns hidden units [r*48, r*48+48) for all 4 gates (192 gate rows).
// W_hh slice lives in registers (384 threads x 48 f32x2 regs = 192 rows x 192 cols).
// h broadcast across the cluster every step via st.shared::cluster + cluster barrier.
__global__ __launch_bounds__(384,1) __cluster_dims__(4,1,1)
void lstm_kernel(const float* __restrict__ Wl)   // W_hh + l*H4*D
{
    __shared__ float h_buf[2][Dd];
    __shared__ float partial[Dd];
    __shared__ float gsm[Dd];

    const int r   = blockIdx.x;        // cluster rank 0..3
    const int b   = blockIdx.y;        // batch
    const int tid = threadIdx.x;       // 0..383
    const int half = (tid >= Dd) ? 1 : 0;
    const int j    = tid - half*Dd;    // 0..191 local gate row
    const int q    = j / 48;
    const int u    = j - q*48;
    const int row_g = q*Dd + r*48 + u; // global gate row in [0,768)

    // W_hh[row_g][half*96 .. half*96+96) as 48 f32x2 register pairs
    unsigned long long w2[48];
    const unsigned long long* wp =
        reinterpret_cast<const unsigned long long*>(Wl + (size_t)row_g*Dd + half*96);
    #pragma unroll
    for (int k=0;k<48;k++) w2[k] = wp[k];

    for (int i = tid; i < 2*Dd; i += 384) (&h_buf[0][0])[i] = 0.f;
    float c = 0.f;
    asm volatile("barrier.cluster.arrive.aligned;\n\t"
                 "barrier.cluster.wait.aligned;" ::: "memory");

    const float* gx_base = g_gx + (size_t)b*Tlen*H4d + row_g;
    float*       h_out   = g_h  + (size_t)b*Tlen*Dd;
    const uint32_t hbuf_addr = smem_u32(&h_buf[0][0]);

    int cur = 0;
    for (int t = 0; t < Tlen; t++){
        float gxv = (half == 0) ? gx_base[(size_t)t*H4d] : 0.f;

        const unsigned long long* hp =
            reinterpret_cast<const unsigned long long*>(&h_buf[cur][half*96]);
        unsigned long long a0=0ULL, a1=0ULL, a2=0ULL, a3=0ULL;
        #pragma unroll
        for (int k=0;k<48;k+=4){
            fma2(a0, w2[k+0], hp[k+0]);
            fma2(a1, w2[k+1], hp[k+1]);
            fma2(a2, w2[k+2], hp[k+2]);
            fma2(a3, w2[k+3], hp[k+3]);
        }
        float2 f0=unpack2(a0), f1=unpack2(a1), f2=unpack2(a2), f3=unpack2(a3);
        float acc = ((f0.x+f0.y)+(f1.x+f1.y)) + ((f2.x+f2.y)+(f3.x+f3.y));

        if (half) partial[j] = acc;
        __syncthreads();
        if (!half) gsm[j] = acc + partial[j] + gxv;
        __syncthreads();

        const int nxt = cur ^ 1;
        if (tid < 48){
            float ig = gsm[tid], fg = gsm[48+tid], gg = gsm[96+tid], og = gsm[144+tid];
            ig = 1.f/(1.f + expf(-ig));
            fg = 1.f/(1.f + expf(-fg));
            gg = tanhf(gg);
            og = 1.f/(1.f + expf(-og));
            c = fg*c + ig*gg;
            float hn = og * tanhf(c);
            int hu = r*48 + tid;
            uint32_t la = hbuf_addr + (uint32_t)(nxt*Dd + hu)*4u;
            #pragma unroll
            for (int rk=0; rk<4; rk++){
                uint32_t ra;
                asm("mapa.shared::cluster.u32 %0, %1, %2;" : "=r"(ra) : "r"(la), "r"(rk));
                asm volatile("st.shared::cluster.f32 [%0], %1;" :: "r"(ra), "f"(hn) : "memory");
            }
            h_out[(size_t)t*Dd + hu] = hn;
        }
        asm volatile("barrier.cluster.arrive.aligned;\n\t"
                     "barrier.cluster.wait.aligned;" ::: "memory");
        cur = nxt;
    }
}

// ---------------- LayerNorm over D=192, write normalized h to output tail -------
__global__ void ln_kernel(const float* __restrict__ gamma,
                          const float* __restrict__ beta,
                          float* __restrict__ out){
    const int row = blockIdx.x;
    const int tid = threadIdx.x;   // 0..191
    float v = g_h[(size_t)row*Dd + tid];
    float s = v, s2 = v*v;
    #pragma unroll
    for (int o=16;o;o>>=1){
        s  += __shfl_down_sync(0xffffffffu, s,  o);
        s2 += __shfl_down_sync(0xffffffffu, s2, o);
    }
    __shared__ float ws[6], ws2[6];
    __shared__ float mean_s, inv_s;
    int w = tid >> 5, lane = tid & 31;
    if (!lane){ ws[w]=s; ws2[w]=s2; }
    __syncthreads();
    if (tid==0){
        float S=0.f, S2=0.f;
        #pragma unroll
        for (int i=0;i<6;i++){ S+=ws[i]; S2+=ws2[i]; }
        float mu = S * (1.f/Dd);
        float var = S2 * (1.f/Dd) - mu*mu;
        mean_s = mu;
        inv_s  = rsqrtf(var + 1e-5f);
    }
    __syncthreads();
    out[(size_t)row*Dd + tid] = (v - mean_s) * inv_s * gamma[tid] + beta[tid];
}

// ---------------- launch ----------------
extern "C" void kernel_launch(void* const* d_in, const int* in_sizes, int n_in,
                              void* d_out, int out_size)
{
    const int*   x     = (const int*)  d_in[0];
    const float* tok   = (const float*)d_in[1];
    const float* pos   = (const float*)d_in[2];
    const float* W_ih  = (const float*)d_in[3];
    const float* W_hh  = (const float*)d_in[4];
    const float* b_ih  = (const float*)d_in[5];
    const float* b_hh  = (const float*)d_in[6];
    const float* gamma = (const float*)d_in[7];
    const float* beta  = (const float*)d_in[8];

    float* out_logits = (float*)d_out;                 // [B,T,V]
    float* out_h      = (float*)d_out + BTV;           // [B,T,D]

    float *ph=nullptr, *pgx=nullptr;
    cudaGetSymbolAddress((void**)&ph,  g_h);
    cudaGetSymbolAddress((void**)&pgx, g_gx);

    embed_kernel<<<BT, Dd>>>(x, tok, pos);

    for (int l = 0; l < Ll; l++){
        gemm_atb<true><<<dim3(H4d/64, BT/64), 256>>>(
            ph, W_ih + (size_t)l*H4d*Dd, b_ih + (size_t)l*H4d, b_hh + (size_t)l*H4d,
            pgx, H4d);
        lstm_kernel<<<dim3(4, Bsz), 384>>>(W_hh + (size_t)l*H4d*Dd);
    }

    ln_kernel<<<BT, Dd>>>(gamma, beta, out_h);

    gemm_atb<false><<<dim3(Vv/64, BT/64), 256>>>(
        out_h, tok, nullptr, nullptr, out_logits, Vv);
}

// round 3
// speedup vs baseline: 1.8120x; 1.8120x over previous
#include <cuda_runtime.h>
#include <cuda_bf16.h>
#include <cstdint>
#include <cmath>

#define Bsz 32
#define Tlen 128
#define Dd 192
#define H4d 768
#define Ll 6
#define Vv 32000
#define BT (Bsz*Tlen)            // 4096
#define BTV ((size_t)BT*(size_t)Vv)
#define KEXT 576                 // 3 x 192 (bf16 hi/lo split)
#define KC 64                    // K chunk (bf16) = 128 bytes/row
#define NCH (KEXT/KC)            // 9

// ---------------- scratch (static device globals; no allocation) ----------------
__device__ __align__(128) float g_h[BT*Dd];
__device__ __align__(128) float g_gx[BT*H4d];
__device__ __align__(128) __nv_bfloat16 g_Aext[BT*KEXT];             // [hi|hi|lo]
__device__ __align__(128) __nv_bfloat16 g_Bext[(size_t)Vv*KEXT];     // [hi|lo|hi]
__device__ __align__(128) __nv_bfloat16 g_Wext[(size_t)Ll*H4d*KEXT]; // [hi|lo|hi]

// ---------------- helpers ----------------
__device__ __forceinline__ uint32_t smem_u32(const void* p){
    uint32_t a;
    asm("{ .reg .u64 t; cvta.to.shared.u64 t, %1; cvt.u32.u64 %0, t; }"
        : "=r"(a) : "l"(p));
    return a;
}
__device__ __forceinline__ float2 unpack2(unsigned long long v){
    unsigned int lo, hi;
    asm("mov.b64 {%0, %1}, %2;" : "=r"(lo), "=r"(hi) : "l"(v));
    return make_float2(__uint_as_float(lo), __uint_as_float(hi));
}
__device__ __forceinline__ void fma2(unsigned long long &d,
                                     unsigned long long a, unsigned long long b){
    asm("fma.rn.f32x2 %0, %1, %2, %3;" : "=l"(d) : "l"(a), "l"(b), "l"(d));
}
__device__ __forceinline__ void cp16(uint32_t s, const void* g){
    asm volatile("cp.async.cg.shared.global [%0], [%1], 16;" :: "r"(s), "l"(g) : "memory");
}
#define SW128(x) ((x) ^ (((x) >> 3) & 0x70))

__device__ __forceinline__ void ldm4(uint32_t &r0, uint32_t &r1,
                                     uint32_t &r2, uint32_t &r3, uint32_t a){
    asm volatile("ldmatrix.sync.aligned.m8n8.x4.shared.b16 {%0,%1,%2,%3}, [%4];"
        : "=r"(r0), "=r"(r1), "=r"(r2), "=r"(r3) : "r"(a));
}
__device__ __forceinline__ void mma16816(float* d, const uint32_t* a,
                                         uint32_t b0, uint32_t b1){
    asm volatile("mma.sync.aligned.m16n8k16.row.col.f32.bf16.bf16.f32 "
        "{%0,%1,%2,%3}, {%4,%5,%6,%7}, {%8,%9}, {%0,%1,%2,%3};"
        : "+f"(d[0]), "+f"(d[1]), "+f"(d[2]), "+f"(d[3])
        : "r"(a[0]), "r"(a[1]), "r"(a[2]), "r"(a[3]), "r"(b0), "r"(b1));
}

// ---------------- embedding ----------------
__global__ void embed_kernel(const int* __restrict__ x,
                             const float* __restrict__ tok,
                             const float* __restrict__ pos){
    int row = blockIdx.x;
    int t   = row & (Tlen - 1);
    int tid = threadIdx.x;
    int v   = x[row];
    g_h[(size_t)row*Dd + tid] = tok[(size_t)v*Dd + tid] + pos[t*Dd + tid];
}

// ---------------- bf16 hi/lo split conversions ----------------
__global__ void conv_A(const float* __restrict__ src, __nv_bfloat16* __restrict__ dst){
    int row = blockIdx.x, c = threadIdx.x;
    float a = src[(size_t)row*Dd + c];
    __nv_bfloat16 hi = __float2bfloat16(a);
    __nv_bfloat16 lo = __float2bfloat16(a - __bfloat162float(hi));
    size_t b = (size_t)row*KEXT;
    dst[b + c] = hi; dst[b + Dd + c] = hi; dst[b + 2*Dd + c] = lo;
}
__global__ void conv_B(const float* __restrict__ src, __nv_bfloat16* __restrict__ dst){
    int row = blockIdx.x, c = threadIdx.x;
    float a = src[(size_t)row*Dd + c];
    __nv_bfloat16 hi = __float2bfloat16(a);
    __nv_bfloat16 lo = __float2bfloat16(a - __bfloat162float(hi));
    size_t b = (size_t)row*KEXT;
    dst[b + c] = hi; dst[b + Dd + c] = lo; dst[b + 2*Dd + c] = hi;
}

// ---------------- mma.sync bf16 GEMM: C[M,N] = Aext[M,576] x Bext[N,576]^T ------
// CTA 128x128, 8 warps (4M x 2N), warp tile 32x64, 3-stage cp.async pipeline,
// SW128 smem + ldmatrix.x4, fp32 accum. 2 CTAs/SM.
#define STAGE_BYTES 32768
#define GEMM_SMEM (3*STAGE_BYTES + 1024)

template<bool BIAS>
__global__ __launch_bounds__(256,2) void mma_gemm(
    const __nv_bfloat16* __restrict__ A,
    const __nv_bfloat16* __restrict__ Bw,
    const float* __restrict__ b1, const float* __restrict__ b2,
    float* __restrict__ C, int N)
{
    extern __shared__ char smem_raw[];
    const uint32_t sbase = (smem_u32(smem_raw) + 1023u) & ~1023u;

    const int t    = threadIdx.x;
    const int lane = t & 31;
    const int wid  = t >> 5;
    const int m0   = blockIdx.y * 128;
    const int n0   = blockIdx.x * 128;
    const int mw   = (wid & 3) * 32;   // warp m offset in tile
    const int nw   = (wid >> 2) * 64;  // warp n offset in tile

    // cp.async per-thread transfers (4 for A, 4 for B per stage)
    uint32_t sAoff[4], sBoff[4];
    const char* gA[4]; const char* gB[4];
    #pragma unroll
    for (int i=0;i<4;i++){
        int idx = t + i*256, row = idx>>3, cc = idx&7;
        uint32_t so = SW128((uint32_t)(row*128 + cc*16));
        sAoff[i] = so;
        sBoff[i] = so + 16384;
        gA[i] = (const char*)(A  + (size_t)(m0+row)*KEXT) + cc*16;
        gB[i] = (const char*)(Bw + (size_t)(n0+row)*KEXT) + cc*16;
    }

    // ldmatrix per-thread base offsets (stage-relative); XOR with ks*32 per k-step
    uint32_t aOff[2], bOff[4];
    {
        int r = lane & 15, hc = (lane >> 4) * 16;
        #pragma unroll
        for (int mt=0; mt<2; mt++)
            aOff[mt] = SW128((uint32_t)((mw + mt*16 + r)*128 + hc));
        #pragma unroll
        for (int p=0; p<4; p++)
            bOff[p] = 16384u + SW128((uint32_t)((nw + p*16 + r)*128 + hc));
    }

    float acc[2][8][4];
    #pragma unroll
    for (int i=0;i<2;i++)
        #pragma unroll
        for (int j=0;j<8;j++)
            #pragma unroll
            for (int k=0;k<4;k++) acc[i][j][k] = 0.f;

    // prologue: stages 0,1
    #pragma unroll
    for (int s=0;s<2;s++){
        uint32_t sb = sbase + s*STAGE_BYTES;
        size_t koff = (size_t)s * (KC*2);
        #pragma unroll
        for (int i=0;i<4;i++) cp16(sb + sAoff[i], gA[i] + koff);
        #pragma unroll
        for (int i=0;i<4;i++) cp16(sb + sBoff[i], gB[i] + koff);
        asm volatile("cp.async.commit_group;" ::: "memory");
    }

    int sidx = 0;
    #pragma unroll 1
    for (int k0 = 0; k0 < NCH; k0++){
        if (k0 == NCH-1) asm volatile("cp.async.wait_group 0;" ::: "memory");
        else             asm volatile("cp.async.wait_group 1;" ::: "memory");
        __syncthreads();

        if (k0 + 2 < NCH){
            int s2 = sidx + 2; if (s2 >= 3) s2 -= 3;
            uint32_t sb = sbase + s2*STAGE_BYTES;
            size_t koff = (size_t)(k0+2) * (KC*2);
            #pragma unroll
            for (int i=0;i<4;i++) cp16(sb + sAoff[i], gA[i] + koff);
            #pragma unroll
            for (int i=0;i<4;i++) cp16(sb + sBoff[i], gB[i] + koff);
            asm volatile("cp.async.commit_group;" ::: "memory");
        }

        const uint32_t sb = sbase + sidx*STAGE_BYTES;
        #pragma unroll
        for (int ks=0; ks<4; ks++){
            const uint32_t kx = ks*32;
            uint32_t a[2][4];
            ldm4(a[0][0], a[0][1], a[0][2], a[0][3], sb + (aOff[0]^kx));
            ldm4(a[1][0], a[1][1], a[1][2], a[1][3], sb + (aOff[1]^kx));
            #pragma unroll
            for (int p=0; p<4; p++){
                uint32_t r0,r1,r2,r3;
                ldm4(r0, r1, r2, r3, sb + (bOff[p]^kx));
                mma16816(acc[0][2*p],   a[0], r0, r2);
                mma16816(acc[0][2*p+1], a[0], r1, r3);
                mma16816(acc[1][2*p],   a[1], r0, r2);
                mma16816(acc[1][2*p+1], a[1], r1, r3);
            }
        }
        sidx++; if (sidx == 3) sidx = 0;
    }

    // epilogue: direct float2 stores (each 32B sector fully covered)
    const int g  = lane >> 2;
    const int tc = (lane & 3) * 2;
    #pragma unroll
    for (int mt=0; mt<2; mt++){
        const int row = m0 + mw + mt*16 + g;
        #pragma unroll
        for (int nt=0; nt<8; nt++){
            const int col = n0 + nw + (nt>>1)*16 + (nt&1)*8 + tc;
            float bb0 = 0.f, bb1 = 0.f;
            if (BIAS){ bb0 = b1[col] + b2[col]; bb1 = b1[col+1] + b2[col+1]; }
            float2 v0 = make_float2(acc[mt][nt][0] + bb0, acc[mt][nt][1] + bb1);
            float2 v1 = make_float2(acc[mt][nt][2] + bb0, acc[mt][nt][3] + bb1);
            *reinterpret_cast<float2*>(C + (size_t)row*N + col)     = v0;
            *reinterpret_cast<float2*>(C + (size_t)(row+8)*N + col) = v1;
        }
    }
}

// ---------------- recurrent scan (unchanged, passing) ---------------------------
__global__ __launch_bounds__(384,1) __cluster_dims__(4,1,1)
void lstm_kernel(const float* __restrict__ Wl)
{
    __shared__ float h_buf[2][Dd];
    __shared__ float partial[Dd];
    __shared__ float gsm[Dd];

    const int r   = blockIdx.x;
    const int b   = blockIdx.y;
    const int tid = threadIdx.x;
    const int half = (tid >= Dd) ? 1 : 0;
    const int j    = tid - half*Dd;
    const int q    = j / 48;
    const int u    = j - q*48;
    const int row_g = q*Dd + r*48 + u;

    unsigned long long w2[48];
    const unsigned long long* wp =
        reinterpret_cast<const unsigned long long*>(Wl + (size_t)row_g*Dd + half*96);
    #pragma unroll
    for (int k=0;k<48;k++) w2[k] = wp[k];

    for (int i = tid; i < 2*Dd; i += 384) (&h_buf[0][0])[i] = 0.f;
    float c = 0.f;
    asm volatile("barrier.cluster.arrive.aligned;\n\t"
                 "barrier.cluster.wait.aligned;" ::: "memory");

    const float* gx_base = g_gx + (size_t)b*Tlen*H4d + row_g;
    float*       h_out   = g_h  + (size_t)b*Tlen*Dd;
    const uint32_t hbuf_addr = smem_u32(&h_buf[0][0]);

    int cur = 0;
    for (int t = 0; t < Tlen; t++){
        float gxv = (half == 0) ? gx_base[(size_t)t*H4d] : 0.f;

        const unsigned long long* hp =
            reinterpret_cast<const unsigned long long*>(&h_buf[cur][half*96]);
        unsigned long long a0=0ULL, a1=0ULL, a2=0ULL, a3=0ULL;
        #pragma unroll
        for (int k=0;k<48;k+=4){
            fma2(a0, w2[k+0], hp[k+0]);
            fma2(a1, w2[k+1], hp[k+1]);
            fma2(a2, w2[k+2], hp[k+2]);
            fma2(a3, w2[k+3], hp[k+3]);
        }
        float2 f0=unpack2(a0), f1=unpack2(a1), f2=unpack2(a2), f3=unpack2(a3);
        float acc = ((f0.x+f0.y)+(f1.x+f1.y)) + ((f2.x+f2.y)+(f3.x+f3.y));

        if (half) partial[j] = acc;
        __syncthreads();
        if (!half) gsm[j] = acc + partial[j] + gxv;
        __syncthreads();

        const int nxt = cur ^ 1;
        if (tid < 48){
            float ig = gsm[tid], fg = gsm[48+tid], gg = gsm[96+tid], og = gsm[144+tid];
            ig = 1.f/(1.f + expf(-ig));
            fg = 1.f/(1.f + expf(-fg));
            gg = tanhf(gg);
            og = 1.f/(1.f + expf(-og));
            c = fg*c + ig*gg;
            float hn = og * tanhf(c);
            int hu = r*48 + tid;
            uint32_t la = hbuf_addr + (uint32_t)(nxt*Dd + hu)*4u;
            #pragma unroll
            for (int rk=0; rk<4; rk++){
                uint32_t ra;
                asm("mapa.shared::cluster.u32 %0, %1, %2;" : "=r"(ra) : "r"(la), "r"(rk));
                asm volatile("st.shared::cluster.f32 [%0], %1;" :: "r"(ra), "f"(hn) : "memory");
            }
            h_out[(size_t)t*Dd + hu] = hn;
        }
        asm volatile("barrier.cluster.arrive.aligned;\n\t"
                     "barrier.cluster.wait.aligned;" ::: "memory");
        cur = nxt;
    }
}

// ---------------- LayerNorm ----------------
__global__ void ln_kernel(const float* __restrict__ gamma,
                          const float* __restrict__ beta,
                          float* __restrict__ out){
    const int row = blockIdx.x;
    const int tid = threadIdx.x;
    float v = g_h[(size_t)row*Dd + tid];
    float s = v, s2 = v*v;
    #pragma unroll
    for (int o=16;o;o>>=1){
        s  += __shfl_down_sync(0xffffffffu, s,  o);
        s2 += __shfl_down_sync(0xffffffffu, s2, o);
    }
    __shared__ float ws[6], ws2[6];
    __shared__ float mean_s, inv_s;
    int w = tid >> 5, lane = tid & 31;
    if (!lane){ ws[w]=s; ws2[w]=s2; }
    __syncthreads();
    if (tid==0){
        float S=0.f, S2=0.f;
        #pragma unroll
        for (int i=0;i<6;i++){ S+=ws[i]; S2+=ws2[i]; }
        float mu = S * (1.f/Dd);
        float var = S2 * (1.f/Dd) - mu*mu;
        mean_s = mu;
        inv_s  = rsqrtf(var + 1e-5f);
    }
    __syncthreads();
    out[(size_t)row*Dd + tid] = (v - mean_s) * inv_s * gamma[tid] + beta[tid];
}

// ---------------- launch ----------------
extern "C" void kernel_launch(void* const* d_in, const int* in_sizes, int n_in,
                              void* d_out, int out_size)
{
    const int*   x     = (const int*)  d_in[0];
    const float* tok   = (const float*)d_in[1];
    const float* pos   = (const float*)d_in[2];
    const float* W_ih  = (const float*)d_in[3];
    const float* W_hh  = (const float*)d_in[4];
    const float* b_ih  = (const float*)d_in[5];
    const float* b_hh  = (const float*)d_in[6];
    const float* gamma = (const float*)d_in[7];
    const float* beta  = (const float*)d_in[8];

    float* out_logits = (float*)d_out;
    float* out_h      = (float*)d_out + BTV;

    float *ph=nullptr, *pgx=nullptr;
    __nv_bfloat16 *pAe=nullptr, *pBe=nullptr, *pWe=nullptr;
    cudaGetSymbolAddress((void**)&ph,  g_h);
    cudaGetSymbolAddress((void**)&pgx, g_gx);
    cudaGetSymbolAddress((void**)&pAe, g_Aext);
    cudaGetSymbolAddress((void**)&pBe, g_Bext);
    cudaGetSymbolAddress((void**)&pWe, g_Wext);

    cudaFuncSetAttribute(mma_gemm<true>,
        cudaFuncAttributeMaxDynamicSharedMemorySize, GEMM_SMEM);
    cudaFuncSetAttribute(mma_gemm<false>,
        cudaFuncAttributeMaxDynamicSharedMemorySize, GEMM_SMEM);

    embed_kernel<<<BT, Dd>>>(x, tok, pos);
    conv_B<<<Vv, Dd>>>(tok, pBe);
    conv_B<<<Ll*H4d, Dd>>>(W_ih, pWe);

    for (int l = 0; l < Ll; l++){
        conv_A<<<BT, Dd>>>(ph, pAe);
        mma_gemm<true><<<dim3(H4d/128, BT/128), 256, GEMM_SMEM>>>(
            pAe, pWe + (size_t)l*H4d*KEXT,
            b_ih + (size_t)l*H4d, b_hh + (size_t)l*H4d,
            pgx, H4d);
        lstm_kernel<<<dim3(4, Bsz), 384>>>(W_hh + (size_t)l*H4d*Dd);
    }

    ln_kernel<<<BT, Dd>>>(gamma, beta, out_h);
    conv_A<<<BT, Dd>>>(out_h, pAe);

    mma_gemm<false><<<dim3(Vv/128, BT/128), 256, GEMM_SMEM>>>(
        pAe, pBe, nullptr, nullptr, out_logits, Vv);
}